// round 6
// baseline (speedup 1.0000x reference)
#include <cuda_runtime.h>
#include <cuda_bf16.h>
#include <math.h>
#include <stdint.h>

#define B_ 32
#define T_ 128
#define E_ 512
#define H_ 256
#define V_ 32000
#define G_ 1024  // 4*H

// ---------------- scratch (device globals; no allocations) ----------------
__device__ float g_Ucat[E_ * G_];        // [E][4H]   2 MB
__device__ float g_Whcat[H_ * G_];       // [H][4H]   1 MB
__device__ float g_bcat[G_];             // [4H]
__device__ float g_xproj[T_ * B_ * G_];  // [T][B][4H] 16 MB
__device__ __nv_bfloat16 g_Ahi[B_ * T_ * H_];   // hs split, [B*T][H] 2 MB
__device__ __nv_bfloat16 g_Alo[B_ * T_ * H_];
__device__ __nv_bfloat16 g_Bthi[V_ * H_];       // W_hy^T split, [V][H] 16 MB
__device__ __nv_bfloat16 g_Btlo[V_ * H_];

// ======================= PTX helpers (sm_90-base only) =====================
__device__ __forceinline__ uint32_t smem_u32(const void* p) {
    uint32_t a;
    asm("{ .reg .u64 t; cvta.to.shared.u64 t, %1; cvt.u32.u64 %0, t; }"
        : "=r"(a) : "l"(p));
    return a;
}

__device__ __forceinline__ void cp_async16(uint32_t saddr, const void* gaddr) {
    asm volatile("cp.async.cg.shared.global [%0], [%1], 16;"
                 :: "r"(saddr), "l"(gaddr) : "memory");
}
__device__ __forceinline__ void cp_commit() {
    asm volatile("cp.async.commit_group;" ::: "memory");
}
template <int N>
__device__ __forceinline__ void cp_wait() {
    asm volatile("cp.async.wait_group %0;" :: "n"(N) : "memory");
}

__device__ __forceinline__ void ldsm_x4(uint32_t& r0, uint32_t& r1,
                                        uint32_t& r2, uint32_t& r3, uint32_t a) {
    asm volatile("ldmatrix.sync.aligned.m8n8.x4.shared.b16 {%0,%1,%2,%3}, [%4];"
                 : "=r"(r0), "=r"(r1), "=r"(r2), "=r"(r3) : "r"(a));
}
__device__ __forceinline__ void ldsm_x2(uint32_t& r0, uint32_t& r1, uint32_t a) {
    asm volatile("ldmatrix.sync.aligned.m8n8.x2.shared.b16 {%0,%1}, [%2];"
                 : "=r"(r0), "=r"(r1) : "r"(a));
}

__device__ __forceinline__ void mma_bf16(float* d, const uint32_t* a,
                                         const uint32_t* b) {
    asm volatile(
        "mma.sync.aligned.m16n8k16.row.col.f32.bf16.bf16.f32 "
        "{%0,%1,%2,%3}, {%4,%5,%6,%7}, {%8,%9}, {%0,%1,%2,%3};"
        : "+f"(d[0]), "+f"(d[1]), "+f"(d[2]), "+f"(d[3])
        : "r"(a[0]), "r"(a[1]), "r"(a[2]), "r"(a[3]), "r"(b[0]), "r"(b[1]));
}

#define CLUSTER_SYNC() do { \
    asm volatile("barrier.cluster.arrive.aligned;" ::: "memory"); \
    asm volatile("barrier.cluster.wait.aligned;" ::: "memory"); \
} while (0)

__device__ __forceinline__ uint32_t mapa_cluster(uint32_t local, uint32_t rank) {
    uint32_t r;
    asm volatile("mapa.shared::cluster.u32 %0, %1, %2;" : "=r"(r) : "r"(local), "r"(rank));
    return r;
}
__device__ __forceinline__ void st_cluster_f32(uint32_t addr, float v) {
    asm volatile("st.shared::cluster.f32 [%0], %1;" :: "r"(addr), "f"(v) : "memory");
}

// ---------------- pack gate weights into concatenated layout ----------------
__global__ void pack_kernel(const float* __restrict__ Ui, const float* __restrict__ Uf,
                            const float* __restrict__ Ug, const float* __restrict__ Uo,
                            const float* __restrict__ Wi, const float* __restrict__ Wf,
                            const float* __restrict__ Wg, const float* __restrict__ Wo,
                            const float* __restrict__ bi, const float* __restrict__ bf,
                            const float* __restrict__ bg, const float* __restrict__ bo)
{
    int i = blockIdx.x * blockDim.x + threadIdx.x;
    if (i < E_ * G_) {
        int e = i / G_, j = i % G_;
        int g = j / H_, jj = j % H_;
        const float* U = (g == 0) ? Ui : (g == 1) ? Uf : (g == 2) ? Ug : Uo;
        g_Ucat[i] = U[e * H_ + jj];
    }
    if (i < H_ * G_) {
        int k = i / G_, j = i % G_;
        int g = j / H_, jj = j % H_;
        const float* W = (g == 0) ? Wi : (g == 1) ? Wf : (g == 2) ? Wg : Wo;
        g_Whcat[i] = W[k * H_ + jj];
    }
    if (i < G_) {
        int g = i / H_, jj = i % H_;
        const float* bb = (g == 0) ? bi : (g == 1) ? bf : (g == 2) ? bg : bo;
        g_bcat[i] = bb[jj];
    }
}

// --------- transpose + bf16-split W_hy [H][V] -> Bt_hi/Bt_lo [V][H] ---------
__global__ void convW_kernel(const float* __restrict__ W_hy)
{
    __shared__ float tl[32][33];
    int v0 = blockIdx.x * 32, k0 = blockIdx.y * 32;
    int tx = threadIdx.x, ty = threadIdx.y;
#pragma unroll
    for (int i = 0; i < 4; i++) {
        int k = ty + i * 8;
        tl[k][tx] = W_hy[(size_t)(k0 + k) * V_ + v0 + tx];
    }
    __syncthreads();
#pragma unroll
    for (int i = 0; i < 4; i++) {
        int vr = ty + i * 8;
        float x = tl[tx][vr];
        __nv_bfloat16 hi = __float2bfloat16(x);
        __nv_bfloat16 lo = __float2bfloat16(x - __bfloat162float(hi));
        size_t o = (size_t)(v0 + vr) * H_ + k0 + tx;
        g_Bthi[o] = hi;
        g_Btlo[o] = lo;
    }
}

// ---------------- fp32 SGEMM for xproj (M=4096,N=1024,K=512) ----------------
__global__ void sgemm_xproj(const float* __restrict__ embed,
                            const int* __restrict__ xind)
{
    constexpr int N = G_;
    constexpr int K = E_;
    __shared__ float As[16][132];
    __shared__ float Bs[16][128];

    const int tid  = threadIdx.x;
    const int row0 = blockIdx.y * 128;
    const int col0 = blockIdx.x * 128;

    const int a_r = tid >> 2;
    const int a_k = (tid & 3) * 4;
    const float* arow[2];
#pragma unroll
    for (int s = 0; s < 2; s++) {
        int r = row0 + a_r + s * 64;
        int t = r / B_, b = r % B_;
        arow[s] = embed + (size_t)xind[b * T_ + t] * E_;
    }
    const int b_r = tid >> 5;
    const int b_c = (tid & 31) * 4;

    float acc[8][8];
#pragma unroll
    for (int i = 0; i < 8; i++)
#pragma unroll
        for (int j = 0; j < 8; j++) acc[i][j] = 0.f;

    const int m0 = (tid >> 4) * 8;
    const int n0 = (tid & 15) * 8;

    for (int k0 = 0; k0 < K; k0 += 16) {
#pragma unroll
        for (int s = 0; s < 2; s++) {
            float4 v = *reinterpret_cast<const float4*>(arow[s] + k0 + a_k);
            int m = a_r + s * 64;
            As[a_k + 0][m] = v.x; As[a_k + 1][m] = v.y;
            As[a_k + 2][m] = v.z; As[a_k + 3][m] = v.w;
        }
#pragma unroll
        for (int s = 0; s < 2; s++) {
            int kk = b_r + s * 8;
            float4 v = *reinterpret_cast<const float4*>(
                g_Ucat + (size_t)(k0 + kk) * N + col0 + b_c);
            *reinterpret_cast<float4*>(&Bs[kk][b_c]) = v;
        }
        __syncthreads();
#pragma unroll
        for (int k = 0; k < 16; k++) {
            float a[8], b[8];
#pragma unroll
            for (int i = 0; i < 8; i++) a[i] = As[k][m0 + i];
#pragma unroll
            for (int j = 0; j < 8; j++) b[j] = Bs[k][n0 + j];
#pragma unroll
            for (int i = 0; i < 8; i++)
#pragma unroll
                for (int j = 0; j < 8; j++) acc[i][j] += a[i] * b[j];
        }
        __syncthreads();
    }
#pragma unroll
    for (int i = 0; i < 8; i++) {
        size_t r = (size_t)(row0 + m0 + i);
#pragma unroll
        for (int j = 0; j < 8; j += 4) {
            float4 v;
            v.x = acc[i][j + 0] + g_bcat[col0 + n0 + j + 0];
            v.y = acc[i][j + 1] + g_bcat[col0 + n0 + j + 1];
            v.z = acc[i][j + 2] + g_bcat[col0 + n0 + j + 2];
            v.w = acc[i][j + 3] + g_bcat[col0 + n0 + j + 3];
            *reinterpret_cast<float4*>(g_xproj + r * N + col0 + n0 + j) = v;
        }
    }
}

// ===== LSTM recurrence: 8-CTA cluster, register-resident weights ===========
// Cluster handles 2 batches. CTA rank owns h-slice [rank*32, rank*32+32)
// -> 128 z-cols (4 gates x 32). 256 threads/CTA:
//   warp w (0..7), lane l: khalf=l>>4, gate=(l>>2)&3, cb=l&3, s=w*4+cb
//   thread holds wreg[128] = Whcat[khalf*128+k][gate*H + rank*32 + s]
// Per step: 256 FFMA -> shfl_xor(16) k-reduce -> 4+4 shfl gate gather ->
// gates (redundant across lanes) -> remote h store (lane>>2 = target rank)
// -> one cluster sync. Zero __syncthreads in the loop.
#define CL_C 8
#define NB 2

__global__ void __cluster_dims__(CL_C, 1, 1) __launch_bounds__(256, 1)
lstm_scan_reg()
{
    __shared__ float h_s[2 * NB * 256];   // [buf][batch][256]

    const int tid  = threadIdx.x;
    const int lane = tid & 31;
    const int w    = tid >> 5;
    uint32_t rank;
    asm("mov.u32 %0, %%cluster_ctarank;" : "=r"(rank));
    const int cid = blockIdx.x / CL_C;

    const int khalf = lane >> 4;          // 0/1: k-range half
    const int gate  = (lane >> 2) & 3;    // gate index
    const int cb    = lane & 3;           // col within warp's 4-col group
    const int s     = w * 4 + cb;         // slice col 0..31
    const int gcol  = gate * H_ + (int)rank * 32 + s;  // col in [G_]

    // register-resident weight slice: wreg[k] = Whcat[khalf*128+k][gcol]
    float wreg[128];
#pragma unroll
    for (int k = 0; k < 128; k++)
        wreg[k] = g_Whcat[(size_t)(khalf * 128 + k) * G_ + gcol];

    for (int i = tid; i < 2 * NB * 256; i += 256) h_s[i] = 0.f;
    CLUSTER_SYNC();

    const int bgl0 = cid * NB;
    const int bgl1 = cid * NB + 1;
    float c0 = 0.f, c1 = 0.f;

    const int gath = (lane & 0x10) | cb;  // gather base lane (same khalf grp)
    const int rk   = lane >> 2;           // broadcast target rank

    for (int t = 0; t < T_; t++) {
        const int p = t & 1;

        // xproj contributions (consumed ~1000cyc later; latency hidden)
        const float* xpb = g_xproj + (size_t)(t * B_) * G_;
        float xp0 = xpb[(size_t)bgl0 * G_ + gcol];
        float xp1 = xpb[(size_t)bgl1 * G_ + gcol];

        // ---- dot over this thread's 128-k half ----
        const float* h0p = h_s + p * (NB * 256) + khalf * 128;
        const float* h1p = h0p + 256;
        float a0 = 0.f, a1 = 0.f;
#pragma unroll
        for (int k4 = 0; k4 < 32; k4++) {
            float4 x0 = *reinterpret_cast<const float4*>(h0p + k4 * 4);
            float4 x1 = *reinterpret_cast<const float4*>(h1p + k4 * 4);
            a0 += x0.x * wreg[4 * k4 + 0]; a1 += x1.x * wreg[4 * k4 + 0];
            a0 += x0.y * wreg[4 * k4 + 1]; a1 += x1.y * wreg[4 * k4 + 1];
            a0 += x0.z * wreg[4 * k4 + 2]; a1 += x1.z * wreg[4 * k4 + 2];
            a0 += x0.w * wreg[4 * k4 + 3]; a1 += x1.w * wreg[4 * k4 + 3];
        }
        // k-half reduce (both halves end with full sum)
        a0 += __shfl_xor_sync(0xFFFFFFFFu, a0, 16);
        a1 += __shfl_xor_sync(0xFFFFFFFFu, a1, 16);
        float z0 = a0 + xp0;
        float z1 = a1 + xp1;

        // gather the 4 gate values for this lane's column
        float zi0 = __shfl_sync(0xFFFFFFFFu, z0, gath);
        float zf0 = __shfl_sync(0xFFFFFFFFu, z0, gath | 4);
        float zg0 = __shfl_sync(0xFFFFFFFFu, z0, gath | 8);
        float zo0 = __shfl_sync(0xFFFFFFFFu, z0, gath | 12);
        float zi1 = __shfl_sync(0xFFFFFFFFu, z1, gath);
        float zf1 = __shfl_sync(0xFFFFFFFFu, z1, gath | 4);
        float zg1 = __shfl_sync(0xFFFFFFFFu, z1, gath | 8);
        float zo1 = __shfl_sync(0xFFFFFFFFu, z1, gath | 12);

        // gates (redundant across gate/khalf lanes; consistent per column)
        float i0 = 1.f / (1.f + expf(-zi0));
        float f0 = 1.f / (1.f + expf(-zf0));
        float g0 = tanhf(zg0);
        float o0 = 1.f / (1.f + expf(-zo0));
        c0 = f0 * c0 + i0 * g0;
        float hh0 = o0 * tanhf(c0);

        float i1 = 1.f / (1.f + expf(-zi1));
        float f1 = 1.f / (1.f + expf(-zf1));
        float g1 = tanhf(zg1);
        float o1 = 1.f / (1.f + expf(-zo1));
        c1 = f1 * c1 + i1 * g1;
        float hh1 = o1 * tanhf(c1);

        // bf16 hi/lo output (unique writers: lanes 0-3 -> b0, 4-7 -> b1)
        if (lane < 8) {
            float hv = (lane < 4) ? hh0 : hh1;
            int bg   = (lane < 4) ? bgl0 : bgl1;
            __nv_bfloat16 hi = __float2bfloat16(hv);
            __nv_bfloat16 lo = __float2bfloat16(hv - __bfloat162float(hi));
            size_t o = ((size_t)bg * T_ + t) * H_ + rank * 32 + s;
            g_Ahi[o] = hi;
            g_Alo[o] = lo;
        }

        // broadcast this CTA's new h slice to all 8 CTAs' next buffer.
        // lane l targets rank l>>2 with its cb's values (redundancy across
        // gate groups exactly covers the 8 ranks).
        {
            const int q = p ^ 1;
            uint32_t la0 = smem_u32(h_s + q * (NB * 256) + (int)rank * 32 + s);
            st_cluster_f32(mapa_cluster(la0, (uint32_t)rk), hh0);
            uint32_t la1 = smem_u32(h_s + q * (NB * 256) + 256 + (int)rank * 32 + s);
            st_cluster_f32(mapa_cluster(la1, (uint32_t)rk), hh1);
        }
        CLUSTER_SYNC();
    }
}

// ======== GEMM2: logits = (Ahi+Alo) @ (Bhi+Blo)^T via mma.sync bf16 =========
#define BK 32
#define SROW 40                       // padded row stride (bf16 elems) = 80B
#define TILE_SB (128 * SROW * 2)      // 10240 B per matrix per stage
#define STAGE_SB (4 * TILE_SB)        // Ahi,Alo,Bhi,Blo
#define GEMM2_SMEM (2 * STAGE_SB)     // 81920 B

__global__ __launch_bounds__(256) void gemm2_kernel(
    float* __restrict__ out, const float* __restrict__ b_y)
{
    extern __shared__ char smem[];
    const uint32_t sb = smem_u32(smem);
    const int tid  = threadIdx.x;
    const int lane = tid & 31;
    const int wid  = tid >> 5;
    const int wm   = wid >> 2;
    const int wn   = wid & 3;

    const int row0 = blockIdx.y * 128;
    const int col0 = blockIdx.x * 128;

    const int ld_r   = tid >> 2;
    const int ld_seg = tid & 3;
    const __nv_bfloat16* gsrc[4];
    gsrc[0] = g_Ahi  + (size_t)(row0)*H_;
    gsrc[1] = g_Alo  + (size_t)(row0)*H_;
    gsrc[2] = g_Bthi + (size_t)(col0)*H_;
    gsrc[3] = g_Btlo + (size_t)(col0)*H_;

    float acc[4][4][4];
#pragma unroll
    for (int i = 0; i < 4; i++)
#pragma unroll
        for (int j = 0; j < 4; j++)
#pragma unroll
            for (int r = 0; r < 4; r++) acc[i][j][r] = 0.f;

#pragma unroll
    for (int m = 0; m < 4; m++)
#pragma unroll
        for (int h = 0; h < 2; h++) {
            int r = ld_r + h * 64;
            uint32_t sa = sb + 0 * STAGE_SB + m * TILE_SB + r * (SROW * 2) + ld_seg * 16;
            cp_async16(sa, gsrc[m] + (size_t)r * H_ + 0 * BK + ld_seg * 8);
        }
    cp_commit();

    for (int s = 0; s < 8; s++) {
        if (s + 1 < 8) {
            int buf = (s + 1) & 1;
#pragma unroll
            for (int m = 0; m < 4; m++)
#pragma unroll
                for (int h = 0; h < 2; h++) {
                    int r = ld_r + h * 64;
                    uint32_t sa = sb + buf * STAGE_SB + m * TILE_SB +
                                  r * (SROW * 2) + ld_seg * 16;
                    cp_async16(sa, gsrc[m] + (size_t)r * H_ + (s + 1) * BK + ld_seg * 8);
                }
            cp_commit();
            cp_wait<1>();
        } else {
            cp_wait<0>();
        }
        __syncthreads();

        const uint32_t base = sb + (s & 1) * STAGE_SB;
        const uint32_t sAhi = base;
        const uint32_t sAlo = base + TILE_SB;
        const uint32_t sBhi = base + 2 * TILE_SB;
        const uint32_t sBlo = base + 3 * TILE_SB;

#pragma unroll
        for (int kk = 0; kk < 2; kk++) {
            uint32_t ahi[4][4], alo[4][4], bhi[4][2], blo[4][2];
            const int a_row_l = (lane & 15);
            const int a_col   = kk * 16 + (lane >> 4) * 8;
#pragma unroll
            for (int mt = 0; mt < 4; mt++) {
                int r = wm * 64 + mt * 16 + a_row_l;
                uint32_t off = (uint32_t)(r * (SROW * 2) + a_col * 2);
                ldsm_x4(ahi[mt][0], ahi[mt][1], ahi[mt][2], ahi[mt][3], sAhi + off);
                ldsm_x4(alo[mt][0], alo[mt][1], alo[mt][2], alo[mt][3], sAlo + off);
            }
            const int b_row_l = (lane & 7);
            const int b_col   = kk * 16 + ((lane >> 3) & 1) * 8;
#pragma unroll
            for (int nt = 0; nt < 4; nt++) {
                int r = wn * 32 + nt * 8 + b_row_l;
                uint32_t off = (uint32_t)(r * (SROW * 2) + b_col * 2);
                ldsm_x2(bhi[nt][0], bhi[nt][1], sBhi + off);
                ldsm_x2(blo[nt][0], blo[nt][1], sBlo + off);
            }
#pragma unroll
            for (int mt = 0; mt < 4; mt++)
#pragma unroll
                for (int nt = 0; nt < 4; nt++) {
                    mma_bf16(acc[mt][nt], ahi[mt], bhi[nt]);
                    mma_bf16(acc[mt][nt], ahi[mt], blo[nt]);
                    mma_bf16(acc[mt][nt], alo[mt], bhi[nt]);
                }
        }
        __syncthreads();
    }

    const int er = lane >> 2;
    const int ec = (lane & 3) * 2;
#pragma unroll
    for (int mt = 0; mt < 4; mt++) {
#pragma unroll
        for (int nt = 0; nt < 4; nt++) {
            int col = col0 + wn * 32 + nt * 8 + ec;
            float bx = b_y[col], by = b_y[col + 1];
            int r0 = row0 + wm * 64 + mt * 16 + er;
            float2 v0 = make_float2(acc[mt][nt][0] + bx, acc[mt][nt][1] + by);
            float2 v1 = make_float2(acc[mt][nt][2] + bx, acc[mt][nt][3] + by);
            *reinterpret_cast<float2*>(out + (size_t)r0 * V_ + col) = v0;
            *reinterpret_cast<float2*>(out + (size_t)(r0 + 8) * V_ + col) = v1;
        }
    }
}

// ---------------- launch ----------------
extern "C" void kernel_launch(void* const* d_in, const int* in_sizes, int n_in,
                              void* d_out, int out_size)
{
    const int*   x_ind = (const int*)  d_in[0];
    const float* embed = (const float*)d_in[1];
    const float* U_i   = (const float*)d_in[2];
    const float* U_f   = (const float*)d_in[3];
    const float* U_g   = (const float*)d_in[4];
    const float* U_o   = (const float*)d_in[5];
    const float* W_i   = (const float*)d_in[6];
    const float* W_f   = (const float*)d_in[7];
    const float* W_g   = (const float*)d_in[8];
    const float* W_o   = (const float*)d_in[9];
    const float* b_i   = (const float*)d_in[10];
    const float* b_f   = (const float*)d_in[11];
    const float* b_g   = (const float*)d_in[12];
    const float* b_o   = (const float*)d_in[13];
    const float* W_hy  = (const float*)d_in[14];
    const float* b_y   = (const float*)d_in[15];
    float* out = (float*)d_out;

    cudaFuncSetAttribute(gemm2_kernel,
                         cudaFuncAttributeMaxDynamicSharedMemorySize, GEMM2_SMEM);

    // 1. pack concatenated gate weights
    {
        int total = E_ * G_;
        pack_kernel<<<(total + 255) / 256, 256>>>(U_i, U_f, U_g, U_o,
                                                  W_i, W_f, W_g, W_o,
                                                  b_i, b_f, b_g, b_o);
    }

    // 2. transpose + split W_hy for the tensor-core logits GEMM
    {
        dim3 grid(V_ / 32, H_ / 32);
        dim3 blk(32, 8);
        convW_kernel<<<grid, blk>>>(W_hy);
    }

    // 3. xproj[T][B][4H] = embed[x_ind] @ Ucat + bcat
    {
        dim3 grid(G_ / 128, (T_ * B_) / 128);
        sgemm_xproj<<<grid, 256>>>(embed, x_ind);
    }

    // 4. LSTM recurrence: 16 clusters x 8 CTAs, register-resident weights
    lstm_scan_reg<<<(B_ / NB) * CL_C, 256>>>();

    // 5. logits[B][T][V] = hs @ W_hy + b_y  (mma.sync bf16, 3-term split)
    {
        dim3 grid(V_ / 128, (B_ * T_) / 128);
        gemm2_kernel<<<grid, 256, GEMM2_SMEM>>>(out, b_y);
    }
}

// round 7
// speedup vs baseline: 1.1245x; 1.1245x over previous
#include <cuda_runtime.h>
#include <cuda_bf16.h>
#include <math.h>
#include <stdint.h>

#define B_ 32
#define T_ 128
#define E_ 512
#define H_ 256
#define V_ 32000
#define G_ 1024  // 4*H

// ---------------- scratch (device globals; no allocations) ----------------
__device__ float g_Ucat[E_ * G_];        // [E][4H]   2 MB
__device__ float g_Whcat[H_ * G_];       // [H][4H]   1 MB
__device__ float g_bcat[G_];             // [4H]
__device__ float g_xproj[T_ * B_ * G_];  // [T][B][4H] 16 MB
__device__ __nv_bfloat16 g_Ahi[B_ * T_ * H_];   // hs split, [B*T][H] 2 MB
__device__ __nv_bfloat16 g_Alo[B_ * T_ * H_];
__device__ __nv_bfloat16 g_Bthi[V_ * H_];       // W_hy^T split, [V][H] 16 MB
__device__ __nv_bfloat16 g_Btlo[V_ * H_];

// ======================= PTX helpers (sm_90-base only) =====================
__device__ __forceinline__ uint32_t smem_u32(const void* p) {
    uint32_t a;
    asm("{ .reg .u64 t; cvta.to.shared.u64 t, %1; cvt.u32.u64 %0, t; }"
        : "=r"(a) : "l"(p));
    return a;
}

__device__ __forceinline__ void cp_async16(uint32_t saddr, const void* gaddr) {
    asm volatile("cp.async.cg.shared.global [%0], [%1], 16;"
                 :: "r"(saddr), "l"(gaddr) : "memory");
}
__device__ __forceinline__ void cp_commit() {
    asm volatile("cp.async.commit_group;" ::: "memory");
}
template <int N>
__device__ __forceinline__ void cp_wait() {
    asm volatile("cp.async.wait_group %0;" :: "n"(N) : "memory");
}

__device__ __forceinline__ void ldsm_x4(uint32_t& r0, uint32_t& r1,
                                        uint32_t& r2, uint32_t& r3, uint32_t a) {
    asm volatile("ldmatrix.sync.aligned.m8n8.x4.shared.b16 {%0,%1,%2,%3}, [%4];"
                 : "=r"(r0), "=r"(r1), "=r"(r2), "=r"(r3) : "r"(a));
}
__device__ __forceinline__ void ldsm_x2(uint32_t& r0, uint32_t& r1, uint32_t a) {
    asm volatile("ldmatrix.sync.aligned.m8n8.x2.shared.b16 {%0,%1}, [%2];"
                 : "=r"(r0), "=r"(r1) : "r"(a));
}

__device__ __forceinline__ void mma_bf16(float* d, const uint32_t* a,
                                         const uint32_t* b) {
    asm volatile(
        "mma.sync.aligned.m16n8k16.row.col.f32.bf16.bf16.f32 "
        "{%0,%1,%2,%3}, {%4,%5,%6,%7}, {%8,%9}, {%0,%1,%2,%3};"
        : "+f"(d[0]), "+f"(d[1]), "+f"(d[2]), "+f"(d[3])
        : "r"(a[0]), "r"(a[1]), "r"(a[2]), "r"(a[3]), "r"(b[0]), "r"(b[1]));
}

#define CLUSTER_SYNC() do { \
    asm volatile("barrier.cluster.arrive.aligned;" ::: "memory"); \
    asm volatile("barrier.cluster.wait.aligned;" ::: "memory"); \
} while (0)

__device__ __forceinline__ uint32_t mapa_cluster(uint32_t local, uint32_t rank) {
    uint32_t r;
    asm volatile("mapa.shared::cluster.u32 %0, %1, %2;" : "=r"(r) : "r"(local), "r"(rank));
    return r;
}
__device__ __forceinline__ void st_cluster_f32(uint32_t addr, float v) {
    asm volatile("st.shared::cluster.f32 [%0], %1;" :: "r"(addr), "f"(v) : "memory");
}

// ---------------- pack gate weights into concatenated layout ----------------
__global__ void pack_kernel(const float* __restrict__ Ui, const float* __restrict__ Uf,
                            const float* __restrict__ Ug, const float* __restrict__ Uo,
                            const float* __restrict__ Wi, const float* __restrict__ Wf,
                            const float* __restrict__ Wg, const float* __restrict__ Wo,
                            const float* __restrict__ bi, const float* __restrict__ bf,
                            const float* __restrict__ bg, const float* __restrict__ bo)
{
    int i = blockIdx.x * blockDim.x + threadIdx.x;
    if (i < E_ * G_) {
        int e = i / G_, j = i % G_;
        int g = j / H_, jj = j % H_;
        const float* U = (g == 0) ? Ui : (g == 1) ? Uf : (g == 2) ? Ug : Uo;
        g_Ucat[i] = U[e * H_ + jj];
    }
    if (i < H_ * G_) {
        int k = i / G_, j = i % G_;
        int g = j / H_, jj = j % H_;
        const float* W = (g == 0) ? Wi : (g == 1) ? Wf : (g == 2) ? Wg : Wo;
        g_Whcat[i] = W[k * H_ + jj];
    }
    if (i < G_) {
        int g = i / H_, jj = i % H_;
        const float* bb = (g == 0) ? bi : (g == 1) ? bf : (g == 2) ? bg : bo;
        g_bcat[i] = bb[jj];
    }
}

// --------- transpose + bf16-split W_hy [H][V] -> Bt_hi/Bt_lo [V][H] ---------
__global__ void convW_kernel(const float* __restrict__ W_hy)
{
    __shared__ float tl[32][33];
    int v0 = blockIdx.x * 32, k0 = blockIdx.y * 32;
    int tx = threadIdx.x, ty = threadIdx.y;
#pragma unroll
    for (int i = 0; i < 4; i++) {
        int k = ty + i * 8;
        tl[k][tx] = W_hy[(size_t)(k0 + k) * V_ + v0 + tx];
    }
    __syncthreads();
#pragma unroll
    for (int i = 0; i < 4; i++) {
        int vr = ty + i * 8;
        float x = tl[tx][vr];
        __nv_bfloat16 hi = __float2bfloat16(x);
        __nv_bfloat16 lo = __float2bfloat16(x - __bfloat162float(hi));
        size_t o = (size_t)(v0 + vr) * H_ + k0 + tx;
        g_Bthi[o] = hi;
        g_Btlo[o] = lo;
    }
}

// ---------------- fp32 SGEMM for xproj (M=4096,N=1024,K=512) ----------------
__global__ void sgemm_xproj(const float* __restrict__ embed,
                            const int* __restrict__ xind)
{
    constexpr int N = G_;
    constexpr int K = E_;
    __shared__ float As[16][132];
    __shared__ float Bs[16][128];

    const int tid  = threadIdx.x;
    const int row0 = blockIdx.y * 128;
    const int col0 = blockIdx.x * 128;

    const int a_r = tid >> 2;
    const int a_k = (tid & 3) * 4;
    const float* arow[2];
#pragma unroll
    for (int s = 0; s < 2; s++) {
        int r = row0 + a_r + s * 64;
        int t = r / B_, b = r % B_;
        arow[s] = embed + (size_t)xind[b * T_ + t] * E_;
    }
    const int b_r = tid >> 5;
    const int b_c = (tid & 31) * 4;

    float acc[8][8];
#pragma unroll
    for (int i = 0; i < 8; i++)
#pragma unroll
        for (int j = 0; j < 8; j++) acc[i][j] = 0.f;

    const int m0 = (tid >> 4) * 8;
    const int n0 = (tid & 15) * 8;

    for (int k0 = 0; k0 < K; k0 += 16) {
#pragma unroll
        for (int s = 0; s < 2; s++) {
            float4 v = *reinterpret_cast<const float4*>(arow[s] + k0 + a_k);
            int m = a_r + s * 64;
            As[a_k + 0][m] = v.x; As[a_k + 1][m] = v.y;
            As[a_k + 2][m] = v.z; As[a_k + 3][m] = v.w;
        }
#pragma unroll
        for (int s = 0; s < 2; s++) {
            int kk = b_r + s * 8;
            float4 v = *reinterpret_cast<const float4*>(
                g_Ucat + (size_t)(k0 + kk) * N + col0 + b_c);
            *reinterpret_cast<float4*>(&Bs[kk][b_c]) = v;
        }
        __syncthreads();
#pragma unroll
        for (int k = 0; k < 16; k++) {
            float a[8], b[8];
#pragma unroll
            for (int i = 0; i < 8; i++) a[i] = As[k][m0 + i];
#pragma unroll
            for (int j = 0; j < 8; j++) b[j] = Bs[k][n0 + j];
#pragma unroll
            for (int i = 0; i < 8; i++)
#pragma unroll
                for (int j = 0; j < 8; j++) acc[i][j] += a[i] * b[j];
        }
        __syncthreads();
    }
#pragma unroll
    for (int i = 0; i < 8; i++) {
        size_t r = (size_t)(row0 + m0 + i);
#pragma unroll
        for (int j = 0; j < 8; j += 4) {
            float4 v;
            v.x = acc[i][j + 0] + g_bcat[col0 + n0 + j + 0];
            v.y = acc[i][j + 1] + g_bcat[col0 + n0 + j + 1];
            v.z = acc[i][j + 2] + g_bcat[col0 + n0 + j + 2];
            v.w = acc[i][j + 3] + g_bcat[col0 + n0 + j + 3];
            *reinterpret_cast<float4*>(g_xproj + r * N + col0 + n0 + j) = v;
        }
    }
}

// ===== LSTM recurrence v3: 8-CTA cluster, reg weights, short phases ========
// Cluster: 2 batches. CTA rank owns h-slice [rank*32, rank*32+32).
// 256 threads: khalf = tid>>7 (k-range half), col = tid&127 (z-col of slice).
// wreg[128] coalesced (consecutive cols -> consecutive gmem addrs).
// Per step: dot (8 indep 32-deep FFMA chains, xproj folded into init) ->
// 1 syncthreads -> gates on 64 threads (4+4 LDS, no shfl) -> direct DSMEM
// broadcast (8 st) -> 1 cluster sync.
#define CL_C 8
#define NB 2

__global__ void __cluster_dims__(CL_C, 1, 1) __launch_bounds__(256, 1)
lstm_scan_v3()
{
    __shared__ float h_s[2 * NB * 256];     // [buf][batch][256]
    __shared__ float zp_s[2 * 128 * 2];     // [khalf][col][batch]

    const int tid = threadIdx.x;
    uint32_t rank;
    asm("mov.u32 %0, %%cluster_ctarank;" : "=r"(rank));
    const int cid = blockIdx.x / CL_C;

    const int khalf = tid >> 7;
    const int col   = tid & 127;
    const int gate  = col >> 5;
    const int s     = col & 31;
    const int gcol  = gate * H_ + (int)rank * 32 + s;

    // register-resident weights (coalesced: lane stride = 4B)
    float wreg[128];
    {
        const float* wp = g_Whcat + (size_t)(khalf * 128) * G_ + gcol;
#pragma unroll
        for (int k = 0; k < 128; k++) wreg[k] = wp[(size_t)k * G_];
    }

    for (int i = tid; i < 2 * NB * 256; i += 256) h_s[i] = 0.f;
    CLUSTER_SYNC();

    const int bgl0 = cid * NB;
    const int bgl1 = bgl0 + 1;

    // gate-phase identity (threads 0..63)
    const int gb = tid >> 5;   // batch (valid when tid<64)
    const int gs = tid & 31;   // slice col
    float c_reg = 0.f;

    for (int t = 0; t < T_; t++) {
        const int p = t & 1;

        // xproj folded into accumulator init (khalf==0 threads only)
        float xp0 = 0.f, xp1 = 0.f;
        if (khalf == 0) {
            const float* xb = g_xproj + (size_t)(t * B_) * G_ + gcol;
            xp0 = xb[(size_t)bgl0 * G_];
            xp1 = xb[(size_t)bgl1 * G_];
        }

        const float* h0p = h_s + p * (NB * 256) + khalf * 128;
        const float* h1p = h0p + 256;
        float a0[4] = {xp0, 0.f, 0.f, 0.f};
        float a1[4] = {xp1, 0.f, 0.f, 0.f};
#pragma unroll
        for (int i = 0; i < 32; i++) {
            const int j = i & 3;
            float4 v0 = *reinterpret_cast<const float4*>(h0p + i * 4);
            float4 v1 = *reinterpret_cast<const float4*>(h1p + i * 4);
            a0[j] += v0.x * wreg[4 * i + 0];
            a0[j] += v0.y * wreg[4 * i + 1];
            a0[j] += v0.z * wreg[4 * i + 2];
            a0[j] += v0.w * wreg[4 * i + 3];
            a1[j] += v1.x * wreg[4 * i + 0];
            a1[j] += v1.y * wreg[4 * i + 1];
            a1[j] += v1.z * wreg[4 * i + 2];
            a1[j] += v1.w * wreg[4 * i + 3];
        }
        float r0 = (a0[0] + a0[1]) + (a0[2] + a0[3]);
        float r1 = (a1[0] + a1[1]) + (a1[2] + a1[3]);
        zp_s[(khalf * 128 + col) * 2 + 0] = r0;
        zp_s[(khalf * 128 + col) * 2 + 1] = r1;
        __syncthreads();

        if (tid < 64) {
            float zi = zp_s[(      gs) * 2 + gb] + zp_s[(128 +      gs) * 2 + gb];
            float zf = zp_s[( 32 + gs) * 2 + gb] + zp_s[(128 + 32 + gs) * 2 + gb];
            float zg = zp_s[( 64 + gs) * 2 + gb] + zp_s[(128 + 64 + gs) * 2 + gb];
            float zo = zp_s[( 96 + gs) * 2 + gb] + zp_s[(128 + 96 + gs) * 2 + gb];
            float ig = 1.f / (1.f + expf(-zi));
            float fg = 1.f / (1.f + expf(-zf));
            float gv = tanhf(zg);
            float og = 1.f / (1.f + expf(-zo));
            c_reg = fg * c_reg + ig * gv;
            float h = og * tanhf(c_reg);

            // bf16 hi/lo output for logits GEMM
            int bg = gb ? bgl1 : bgl0;
            __nv_bfloat16 hi = __float2bfloat16(h);
            __nv_bfloat16 lo = __float2bfloat16(h - __bfloat162float(hi));
            size_t o = ((size_t)bg * T_ + t) * H_ + rank * 32 + gs;
            g_Ahi[o] = hi;
            g_Alo[o] = lo;

            // direct broadcast to all 8 CTAs' next h buffer
            const int q = p ^ 1;
            uint32_t la = smem_u32(h_s + q * (NB * 256) + gb * 256 +
                                   (int)rank * 32 + gs);
#pragma unroll
            for (int rk = 0; rk < CL_C; rk++)
                st_cluster_f32(mapa_cluster(la, (uint32_t)rk), h);
        }
        CLUSTER_SYNC();
    }
}

// ======== GEMM2: logits = (Ahi+Alo) @ (Bhi+Blo)^T via mma.sync bf16 =========
#define BK 32
#define SROW 40                       // padded row stride (bf16 elems) = 80B
#define TILE_SB (128 * SROW * 2)      // 10240 B per matrix per stage
#define STAGE_SB (4 * TILE_SB)        // Ahi,Alo,Bhi,Blo
#define GEMM2_SMEM (2 * STAGE_SB)     // 81920 B

__global__ __launch_bounds__(256, 2) void gemm2_kernel(
    float* __restrict__ out, const float* __restrict__ b_y)
{
    extern __shared__ char smem[];
    const uint32_t sb = smem_u32(smem);
    const int tid  = threadIdx.x;
    const int lane = tid & 31;
    const int wid  = tid >> 5;
    const int wm   = wid >> 2;
    const int wn   = wid & 3;

    const int row0 = blockIdx.y * 128;
    const int col0 = blockIdx.x * 128;

    const int ld_r   = tid >> 2;
    const int ld_seg = tid & 3;
    const __nv_bfloat16* gsrc[4];
    gsrc[0] = g_Ahi  + (size_t)(row0)*H_;
    gsrc[1] = g_Alo  + (size_t)(row0)*H_;
    gsrc[2] = g_Bthi + (size_t)(col0)*H_;
    gsrc[3] = g_Btlo + (size_t)(col0)*H_;

    float acc[4][4][4];
#pragma unroll
    for (int i = 0; i < 4; i++)
#pragma unroll
        for (int j = 0; j < 4; j++)
#pragma unroll
            for (int r = 0; r < 4; r++) acc[i][j][r] = 0.f;

#pragma unroll
    for (int m = 0; m < 4; m++)
#pragma unroll
        for (int h = 0; h < 2; h++) {
            int r = ld_r + h * 64;
            uint32_t sa = sb + 0 * STAGE_SB + m * TILE_SB + r * (SROW * 2) + ld_seg * 16;
            cp_async16(sa, gsrc[m] + (size_t)r * H_ + 0 * BK + ld_seg * 8);
        }
    cp_commit();

    for (int s = 0; s < 8; s++) {
        if (s + 1 < 8) {
            int buf = (s + 1) & 1;
#pragma unroll
            for (int m = 0; m < 4; m++)
#pragma unroll
                for (int h = 0; h < 2; h++) {
                    int r = ld_r + h * 64;
                    uint32_t sa = sb + buf * STAGE_SB + m * TILE_SB +
                                  r * (SROW * 2) + ld_seg * 16;
                    cp_async16(sa, gsrc[m] + (size_t)r * H_ + (s + 1) * BK + ld_seg * 8);
                }
            cp_commit();
            cp_wait<1>();
        } else {
            cp_wait<0>();
        }
        __syncthreads();

        const uint32_t base = sb + (s & 1) * STAGE_SB;
        const uint32_t sAhi = base;
        const uint32_t sAlo = base + TILE_SB;
        const uint32_t sBhi = base + 2 * TILE_SB;
        const uint32_t sBlo = base + 3 * TILE_SB;

#pragma unroll
        for (int kk = 0; kk < 2; kk++) {
            uint32_t bhi[4][2], blo[4][2];
            const int b_row_l = (lane & 7);
            const int b_col   = kk * 16 + ((lane >> 3) & 1) * 8;
#pragma unroll
            for (int nt = 0; nt < 4; nt++) {
                int r = wn * 32 + nt * 8 + b_row_l;
                uint32_t off = (uint32_t)(r * (SROW * 2) + b_col * 2);
                ldsm_x2(bhi[nt][0], bhi[nt][1], sBhi + off);
                ldsm_x2(blo[nt][0], blo[nt][1], sBlo + off);
            }
            const int a_row_l = (lane & 15);
            const int a_col   = kk * 16 + (lane >> 4) * 8;
#pragma unroll
            for (int mt = 0; mt < 4; mt++) {
                uint32_t ahi[4], alo[4];
                int r = wm * 64 + mt * 16 + a_row_l;
                uint32_t off = (uint32_t)(r * (SROW * 2) + a_col * 2);
                ldsm_x4(ahi[0], ahi[1], ahi[2], ahi[3], sAhi + off);
                ldsm_x4(alo[0], alo[1], alo[2], alo[3], sAlo + off);
#pragma unroll
                for (int nt = 0; nt < 4; nt++) {
                    mma_bf16(acc[mt][nt], ahi, bhi[nt]);
                    mma_bf16(acc[mt][nt], ahi, blo[nt]);
                    mma_bf16(acc[mt][nt], alo, bhi[nt]);
                }
            }
        }
        __syncthreads();
    }

    const int er = lane >> 2;
    const int ec = (lane & 3) * 2;
#pragma unroll
    for (int mt = 0; mt < 4; mt++) {
#pragma unroll
        for (int nt = 0; nt < 4; nt++) {
            int col = col0 + wn * 32 + nt * 8 + ec;
            float bx = b_y[col], by = b_y[col + 1];
            int r0 = row0 + wm * 64 + mt * 16 + er;
            float2 v0 = make_float2(acc[mt][nt][0] + bx, acc[mt][nt][1] + by);
            float2 v1 = make_float2(acc[mt][nt][2] + bx, acc[mt][nt][3] + by);
            *reinterpret_cast<float2*>(out + (size_t)r0 * V_ + col) = v0;
            *reinterpret_cast<float2*>(out + (size_t)(r0 + 8) * V_ + col) = v1;
        }
    }
}

// ---------------- launch ----------------
extern "C" void kernel_launch(void* const* d_in, const int* in_sizes, int n_in,
                              void* d_out, int out_size)
{
    const int*   x_ind = (const int*)  d_in[0];
    const float* embed = (const float*)d_in[1];
    const float* U_i   = (const float*)d_in[2];
    const float* U_f   = (const float*)d_in[3];
    const float* U_g   = (const float*)d_in[4];
    const float* U_o   = (const float*)d_in[5];
    const float* W_i   = (const float*)d_in[6];
    const float* W_f   = (const float*)d_in[7];
    const float* W_g   = (const float*)d_in[8];
    const float* W_o   = (const float*)d_in[9];
    const float* b_i   = (const float*)d_in[10];
    const float* b_f   = (const float*)d_in[11];
    const float* b_g   = (const float*)d_in[12];
    const float* b_o   = (const float*)d_in[13];
    const float* W_hy  = (const float*)d_in[14];
    const float* b_y   = (const float*)d_in[15];
    float* out = (float*)d_out;

    cudaFuncSetAttribute(gemm2_kernel,
                         cudaFuncAttributeMaxDynamicSharedMemorySize, GEMM2_SMEM);

    // 1. pack concatenated gate weights
    {
        int total = E_ * G_;
        pack_kernel<<<(total + 255) / 256, 256>>>(U_i, U_f, U_g, U_o,
                                                  W_i, W_f, W_g, W_o,
                                                  b_i, b_f, b_g, b_o);
    }

    // 2. transpose + split W_hy for the tensor-core logits GEMM
    {
        dim3 grid(V_ / 32, H_ / 32);
        dim3 blk(32, 8);
        convW_kernel<<<grid, blk>>>(W_hy);
    }

    // 3. xproj[T][B][4H] = embed[x_ind] @ Ucat + bcat
    {
        dim3 grid(G_ / 128, (T_ * B_) / 128);
        sgemm_xproj<<<grid, 256>>>(embed, x_ind);
    }

    // 4. LSTM recurrence v3
    lstm_scan_v3<<<(B_ / NB) * CL_C, 256>>>();

    // 5. logits[B][T][V] = hs @ W_hy + b_y  (mma.sync bf16, 3-term split)
    {
        dim3 grid(V_ / 128, (B_ * T_) / 128);
        gemm2_kernel<<<grid, 256, GEMM2_SMEM>>>(out, b_y);
    }
}

// round 9
// speedup vs baseline: 1.1924x; 1.0603x over previous
#include <cuda_runtime.h>
#include <cuda_bf16.h>
#include <math.h>
#include <stdint.h>

#define B_ 32
#define T_ 128
#define E_ 512
#define H_ 256
#define V_ 32000
#define G_ 1024  // 4*H

// ---------------- scratch (device globals; no allocations) ----------------
__device__ float g_Whcat[H_ * G_];       // [H][4H]   1 MB
__device__ float g_bcat[G_];             // [4H]
__device__ float g_xproj[T_ * B_ * G_];  // [T][B][4H] 16 MB
__device__ __nv_bfloat16 g_Xhi[T_ * B_ * E_];   // gathered embed split, 4 MB
__device__ __nv_bfloat16 g_Xlo[T_ * B_ * E_];
__device__ __nv_bfloat16 g_Uthi[G_ * E_];       // U^T split, [G][E] 1 MB
__device__ __nv_bfloat16 g_Utlo[G_ * E_];
__device__ __nv_bfloat16 g_Ahi[B_ * T_ * H_];   // hs split, [B*T][H] 2 MB
__device__ __nv_bfloat16 g_Alo[B_ * T_ * H_];
__device__ __nv_bfloat16 g_Bthi[V_ * H_];       // W_hy^T split, [V][H] 16 MB
__device__ __nv_bfloat16 g_Btlo[V_ * H_];

// ======================= PTX helpers (sm_90-base only) =====================
__device__ __forceinline__ uint32_t smem_u32(const void* p) {
    uint32_t a;
    asm("{ .reg .u64 t; cvta.to.shared.u64 t, %1; cvt.u32.u64 %0, t; }"
        : "=r"(a) : "l"(p));
    return a;
}

__device__ __forceinline__ void cp_async16(uint32_t saddr, const void* gaddr) {
    asm volatile("cp.async.cg.shared.global [%0], [%1], 16;"
                 :: "r"(saddr), "l"(gaddr) : "memory");
}
__device__ __forceinline__ void cp_commit() {
    asm volatile("cp.async.commit_group;" ::: "memory");
}
template <int N>
__device__ __forceinline__ void cp_wait() {
    asm volatile("cp.async.wait_group %0;" :: "n"(N) : "memory");
}

__device__ __forceinline__ void ldsm_x4(uint32_t& r0, uint32_t& r1,
                                        uint32_t& r2, uint32_t& r3, uint32_t a) {
    asm volatile("ldmatrix.sync.aligned.m8n8.x4.shared.b16 {%0,%1,%2,%3}, [%4];"
                 : "=r"(r0), "=r"(r1), "=r"(r2), "=r"(r3) : "r"(a));
}
__device__ __forceinline__ void ldsm_x2(uint32_t& r0, uint32_t& r1, uint32_t a) {
    asm volatile("ldmatrix.sync.aligned.m8n8.x2.shared.b16 {%0,%1}, [%2];"
                 : "=r"(r0), "=r"(r1) : "r"(a));
}

__device__ __forceinline__ void mma_bf16(float* d, const uint32_t* a,
                                         const uint32_t* b) {
    asm volatile(
        "mma.sync.aligned.m16n8k16.row.col.f32.bf16.bf16.f32 "
        "{%0,%1,%2,%3}, {%4,%5,%6,%7}, {%8,%9}, {%0,%1,%2,%3};"
        : "+f"(d[0]), "+f"(d[1]), "+f"(d[2]), "+f"(d[3])
        : "r"(a[0]), "r"(a[1]), "r"(a[2]), "r"(a[3]), "r"(b[0]), "r"(b[1]));
}

#define CLUSTER_SYNC() do { \
    asm volatile("barrier.cluster.arrive.aligned;" ::: "memory"); \
    asm volatile("barrier.cluster.wait.aligned;" ::: "memory"); \
} while (0)

__device__ __forceinline__ uint32_t mapa_cluster(uint32_t local, uint32_t rank) {
    uint32_t r;
    asm volatile("mapa.shared::cluster.u32 %0, %1, %2;" : "=r"(r) : "r"(local), "r"(rank));
    return r;
}
__device__ __forceinline__ void st_cluster_f32(uint32_t addr, float v) {
    asm volatile("st.shared::cluster.f32 [%0], %1;" :: "r"(addr), "f"(v) : "memory");
}

// ---------------- pack Whcat + bias (scan uses fp32 weights) ---------------
__global__ void pack_kernel(const float* __restrict__ Wi, const float* __restrict__ Wf,
                            const float* __restrict__ Wg, const float* __restrict__ Wo,
                            const float* __restrict__ bi, const float* __restrict__ bf,
                            const float* __restrict__ bg, const float* __restrict__ bo)
{
    int i = blockIdx.x * blockDim.x + threadIdx.x;
    if (i < H_ * G_) {
        int k = i / G_, j = i % G_;
        int g = j / H_, jj = j % H_;
        const float* W = (g == 0) ? Wi : (g == 1) ? Wf : (g == 2) ? Wg : Wo;
        g_Whcat[i] = W[k * H_ + jj];
    }
    if (i < G_) {
        int g = i / H_, jj = i % H_;
        const float* bb = (g == 0) ? bi : (g == 1) ? bf : (g == 2) ? bg : bo;
        g_bcat[i] = bb[jj];
    }
}

// --------- transpose + bf16-split W_hy [H][V] -> Bt_hi/Bt_lo [V][H] ---------
__global__ void convW_kernel(const float* __restrict__ W_hy)
{
    __shared__ float tl[32][33];
    int v0 = blockIdx.x * 32, k0 = blockIdx.y * 32;
    int tx = threadIdx.x, ty = threadIdx.y;
#pragma unroll
    for (int i = 0; i < 4; i++) {
        int k = ty + i * 8;
        tl[k][tx] = W_hy[(size_t)(k0 + k) * V_ + v0 + tx];
    }
    __syncthreads();
#pragma unroll
    for (int i = 0; i < 4; i++) {
        int vr = ty + i * 8;
        float x = tl[tx][vr];
        __nv_bfloat16 hi = __float2bfloat16(x);
        __nv_bfloat16 lo = __float2bfloat16(x - __bfloat162float(hi));
        size_t o = (size_t)(v0 + vr) * H_ + k0 + tx;
        g_Bthi[o] = hi;
        g_Btlo[o] = lo;
    }
}

// --------- transpose + bf16-split gate U [E][H] -> Ut_hi/lo [G][E] ----------
__global__ void convU_kernel(const float* __restrict__ Ui, const float* __restrict__ Uf,
                             const float* __restrict__ Ug, const float* __restrict__ Uo)
{
    __shared__ float tl[32][33];
    const int gate = blockIdx.z;
    const float* U = (gate == 0) ? Ui : (gate == 1) ? Uf : (gate == 2) ? Ug : Uo;
    int h0 = blockIdx.x * 32, e0 = blockIdx.y * 32;
    int tx = threadIdx.x, ty = threadIdx.y;
#pragma unroll
    for (int i = 0; i < 4; i++) {
        int e = ty + i * 8;
        tl[e][tx] = U[(size_t)(e0 + e) * H_ + h0 + tx];
    }
    __syncthreads();
#pragma unroll
    for (int i = 0; i < 4; i++) {
        int hr = ty + i * 8;
        float x = tl[tx][hr];
        __nv_bfloat16 hi = __float2bfloat16(x);
        __nv_bfloat16 lo = __float2bfloat16(x - __bfloat162float(hi));
        size_t o = (size_t)(gate * H_ + h0 + hr) * E_ + e0 + tx;
        g_Uthi[o] = hi;
        g_Utlo[o] = lo;
    }
}

// --------- gather embed rows + bf16-split: X[r=t*B+b][E] ----------
__global__ void gatherX_kernel(const float* __restrict__ embed,
                               const int* __restrict__ xind)
{
    const int r = blockIdx.x;          // 0..T*B-1, r = t*B + b
    const int t = r / B_, b = r % B_;
    const float* src = embed + (size_t)xind[b * T_ + t] * E_;
    for (int i = threadIdx.x * 4; i < E_; i += blockDim.x * 4) {
        float4 v = *reinterpret_cast<const float4*>(src + i);
        __nv_bfloat16 h0 = __float2bfloat16(v.x);
        __nv_bfloat16 h1 = __float2bfloat16(v.y);
        __nv_bfloat16 h2 = __float2bfloat16(v.z);
        __nv_bfloat16 h3 = __float2bfloat16(v.w);
        __nv_bfloat162 hi01 = {h0, h1}, hi23 = {h2, h3};
        __nv_bfloat162 lo01 = {__float2bfloat16(v.x - __bfloat162float(h0)),
                               __float2bfloat16(v.y - __bfloat162float(h1))};
        __nv_bfloat162 lo23 = {__float2bfloat16(v.z - __bfloat162float(h2)),
                               __float2bfloat16(v.w - __bfloat162float(h3))};
        *reinterpret_cast<__nv_bfloat162*>(g_Xhi + (size_t)r * E_ + i)     = hi01;
        *reinterpret_cast<__nv_bfloat162*>(g_Xhi + (size_t)r * E_ + i + 2) = hi23;
        *reinterpret_cast<__nv_bfloat162*>(g_Xlo + (size_t)r * E_ + i)     = lo01;
        *reinterpret_cast<__nv_bfloat162*>(g_Xlo + (size_t)r * E_ + i + 2) = lo23;
    }
}

// ===== LSTM recurrence v3 (unchanged; device globals referenced in-kernel) ==
#define CL_C 8
#define NB 2

__global__ void __cluster_dims__(CL_C, 1, 1) __launch_bounds__(256, 1)
lstm_scan_v3()
{
    __shared__ float h_s[2 * NB * 256];     // [buf][batch][256]
    __shared__ float zp_s[2 * 128 * 2];     // [khalf][col][batch]

    const int tid = threadIdx.x;
    uint32_t rank;
    asm("mov.u32 %0, %%cluster_ctarank;" : "=r"(rank));
    const int cid = blockIdx.x / CL_C;

    const int khalf = tid >> 7;
    const int col   = tid & 127;
    const int gate  = col >> 5;
    const int s     = col & 31;
    const int gcol  = gate * H_ + (int)rank * 32 + s;

    float wreg[128];
    {
        const float* wp = g_Whcat + (size_t)(khalf * 128) * G_ + gcol;
#pragma unroll
        for (int k = 0; k < 128; k++) wreg[k] = wp[(size_t)k * G_];
    }

    for (int i = tid; i < 2 * NB * 256; i += 256) h_s[i] = 0.f;
    CLUSTER_SYNC();

    const int bgl0 = cid * NB;
    const int bgl1 = bgl0 + 1;

    const int gb = tid >> 5;   // batch (valid when tid<64)
    const int gs = tid & 31;   // slice col
    float c_reg = 0.f;

    for (int t = 0; t < T_; t++) {
        const int p = t & 1;

        float xp0 = 0.f, xp1 = 0.f;
        if (khalf == 0) {
            const float* xb = g_xproj + (size_t)(t * B_) * G_ + gcol;
            xp0 = xb[(size_t)bgl0 * G_];
            xp1 = xb[(size_t)bgl1 * G_];
        }

        const float* h0p = h_s + p * (NB * 256) + khalf * 128;
        const float* h1p = h0p + 256;
        float a0[4] = {xp0, 0.f, 0.f, 0.f};
        float a1[4] = {xp1, 0.f, 0.f, 0.f};
#pragma unroll
        for (int i = 0; i < 32; i++) {
            const int j = i & 3;
            float4 v0 = *reinterpret_cast<const float4*>(h0p + i * 4);
            float4 v1 = *reinterpret_cast<const float4*>(h1p + i * 4);
            a0[j] += v0.x * wreg[4 * i + 0];
            a0[j] += v0.y * wreg[4 * i + 1];
            a0[j] += v0.z * wreg[4 * i + 2];
            a0[j] += v0.w * wreg[4 * i + 3];
            a1[j] += v1.x * wreg[4 * i + 0];
            a1[j] += v1.y * wreg[4 * i + 1];
            a1[j] += v1.z * wreg[4 * i + 2];
            a1[j] += v1.w * wreg[4 * i + 3];
        }
        float r0 = (a0[0] + a0[1]) + (a0[2] + a0[3]);
        float r1 = (a1[0] + a1[1]) + (a1[2] + a1[3]);
        zp_s[(khalf * 128 + col) * 2 + 0] = r0;
        zp_s[(khalf * 128 + col) * 2 + 1] = r1;
        __syncthreads();

        if (tid < 64) {
            float zi = zp_s[(      gs) * 2 + gb] + zp_s[(128 +      gs) * 2 + gb];
            float zf = zp_s[( 32 + gs) * 2 + gb] + zp_s[(128 + 32 + gs) * 2 + gb];
            float zg = zp_s[( 64 + gs) * 2 + gb] + zp_s[(128 + 64 + gs) * 2 + gb];
            float zo = zp_s[( 96 + gs) * 2 + gb] + zp_s[(128 + 96 + gs) * 2 + gb];
            float ig = 1.f / (1.f + expf(-zi));
            float fg = 1.f / (1.f + expf(-zf));
            float gv = tanhf(zg);
            float og = 1.f / (1.f + expf(-zo));
            c_reg = fg * c_reg + ig * gv;
            float h = og * tanhf(c_reg);

            int bg = gb ? bgl1 : bgl0;
            __nv_bfloat16 hi = __float2bfloat16(h);
            __nv_bfloat16 lo = __float2bfloat16(h - __bfloat162float(hi));
            size_t o = ((size_t)bg * T_ + t) * H_ + rank * 32 + gs;
            g_Ahi[o] = hi;
            g_Alo[o] = lo;

            const int q = p ^ 1;
            uint32_t la = smem_u32(h_s + q * (NB * 256) + gb * 256 +
                                   (int)rank * 32 + gs);
#pragma unroll
            for (int rk = 0; rk < CL_C; rk++)
                st_cluster_f32(mapa_cluster(la, (uint32_t)rk), h);
        }
        CLUSTER_SYNC();
    }
}

// ======== HGEMM template: binds device globals INSIDE device code ==========
// MODE 0: g_xproj[T*B][G]  = (Xhi+Xlo) @ (Uthi+Utlo)^T + g_bcat   (K=512)
// MODE 1: out[B*T][V]      = (Ahi+Alo) @ (Bthi+Btlo)^T + b_y      (K=256)
#define BK 32
#define SROW 40                       // padded row stride (bf16 elems) = 80B
#define TILE_SB (128 * SROW * 2)      // 10240 B per matrix per stage
#define STAGE_SB (4 * TILE_SB)        // Ahi,Alo,Bhi,Blo
#define GEMM_SMEM (2 * STAGE_SB)      // 81920 B

template <int MODE>
__global__ __launch_bounds__(256, 2) void hgemm_kernel(
    const float* __restrict__ bias_ext, float* __restrict__ out_ext)
{
    constexpr int NDIM = (MODE == 0) ? G_ : V_;
    constexpr int KDIM = (MODE == 0) ? E_ : H_;
    constexpr int NSTG = KDIM / BK;

    extern __shared__ char smem[];
    const uint32_t sb = smem_u32(smem);
    const int tid  = threadIdx.x;
    const int lane = tid & 31;
    const int wid  = tid >> 5;
    const int wm   = wid >> 2;
    const int wn   = wid & 3;

    const int row0 = blockIdx.y * 128;
    const int col0 = blockIdx.x * 128;

    const __nv_bfloat16* Ahi = (MODE == 0) ? g_Xhi  : g_Ahi;
    const __nv_bfloat16* Alo = (MODE == 0) ? g_Xlo  : g_Alo;
    const __nv_bfloat16* Bhi = (MODE == 0) ? g_Uthi : g_Bthi;
    const __nv_bfloat16* Blo = (MODE == 0) ? g_Utlo : g_Btlo;
    const float* bias = (MODE == 0) ? g_bcat  : bias_ext;
    float*       out  = (MODE == 0) ? g_xproj : out_ext;

    const int ld_r   = tid >> 2;
    const int ld_seg = tid & 3;
    const __nv_bfloat16* gsrc[4];
    gsrc[0] = Ahi + (size_t)(row0)*KDIM;
    gsrc[1] = Alo + (size_t)(row0)*KDIM;
    gsrc[2] = Bhi + (size_t)(col0)*KDIM;
    gsrc[3] = Blo + (size_t)(col0)*KDIM;

    float acc[4][4][4];
#pragma unroll
    for (int i = 0; i < 4; i++)
#pragma unroll
        for (int j = 0; j < 4; j++)
#pragma unroll
            for (int r = 0; r < 4; r++) acc[i][j][r] = 0.f;

#pragma unroll
    for (int m = 0; m < 4; m++)
#pragma unroll
        for (int h = 0; h < 2; h++) {
            int r = ld_r + h * 64;
            uint32_t sa = sb + 0 * STAGE_SB + m * TILE_SB + r * (SROW * 2) + ld_seg * 16;
            cp_async16(sa, gsrc[m] + (size_t)r * KDIM + 0 * BK + ld_seg * 8);
        }
    cp_commit();

    for (int s = 0; s < NSTG; s++) {
        if (s + 1 < NSTG) {
            int buf = (s + 1) & 1;
#pragma unroll
            for (int m = 0; m < 4; m++)
#pragma unroll
                for (int h = 0; h < 2; h++) {
                    int r = ld_r + h * 64;
                    uint32_t sa = sb + buf * STAGE_SB + m * TILE_SB +
                                  r * (SROW * 2) + ld_seg * 16;
                    cp_async16(sa, gsrc[m] + (size_t)r * KDIM + (s + 1) * BK + ld_seg * 8);
                }
            cp_commit();
            cp_wait<1>();
        } else {
            cp_wait<0>();
        }
        __syncthreads();

        const uint32_t base = sb + (s & 1) * STAGE_SB;
        const uint32_t sAhi = base;
        const uint32_t sAlo = base + TILE_SB;
        const uint32_t sBhi = base + 2 * TILE_SB;
        const uint32_t sBlo = base + 3 * TILE_SB;

#pragma unroll
        for (int kk = 0; kk < 2; kk++) {
            uint32_t bhi[4][2], blo[4][2];
            const int b_row_l = (lane & 7);
            const int b_col   = kk * 16 + ((lane >> 3) & 1) * 8;
#pragma unroll
            for (int nt = 0; nt < 4; nt++) {
                int r = wn * 32 + nt * 8 + b_row_l;
                uint32_t off = (uint32_t)(r * (SROW * 2) + b_col * 2);
                ldsm_x2(bhi[nt][0], bhi[nt][1], sBhi + off);
                ldsm_x2(blo[nt][0], blo[nt][1], sBlo + off);
            }
            const int a_row_l = (lane & 15);
            const int a_col   = kk * 16 + (lane >> 4) * 8;
#pragma unroll
            for (int mt = 0; mt < 4; mt++) {
                uint32_t ahi[4], alo[4];
                int r = wm * 64 + mt * 16 + a_row_l;
                uint32_t off = (uint32_t)(r * (SROW * 2) + a_col * 2);
                ldsm_x4(ahi[0], ahi[1], ahi[2], ahi[3], sAhi + off);
                ldsm_x4(alo[0], alo[1], alo[2], alo[3], sAlo + off);
#pragma unroll
                for (int nt = 0; nt < 4; nt++) {
                    mma_bf16(acc[mt][nt], ahi, bhi[nt]);
                    mma_bf16(acc[mt][nt], ahi, blo[nt]);
                    mma_bf16(acc[mt][nt], alo, bhi[nt]);
                }
            }
        }
        __syncthreads();
    }

    const int er = lane >> 2;
    const int ec = (lane & 3) * 2;
#pragma unroll
    for (int mt = 0; mt < 4; mt++) {
#pragma unroll
        for (int nt = 0; nt < 4; nt++) {
            int col = col0 + wn * 32 + nt * 8 + ec;
            float bx = bias[col], by = bias[col + 1];
            int r0 = row0 + wm * 64 + mt * 16 + er;
            float2 v0 = make_float2(acc[mt][nt][0] + bx, acc[mt][nt][1] + by);
            float2 v1 = make_float2(acc[mt][nt][2] + bx, acc[mt][nt][3] + by);
            *reinterpret_cast<float2*>(out + (size_t)r0 * NDIM + col) = v0;
            *reinterpret_cast<float2*>(out + (size_t)(r0 + 8) * NDIM + col) = v1;
        }
    }
}

// ---------------- launch ----------------
extern "C" void kernel_launch(void* const* d_in, const int* in_sizes, int n_in,
                              void* d_out, int out_size)
{
    const int*   x_ind = (const int*)  d_in[0];
    const float* embed = (const float*)d_in[1];
    const float* U_i   = (const float*)d_in[2];
    const float* U_f   = (const float*)d_in[3];
    const float* U_g   = (const float*)d_in[4];
    const float* U_o   = (const float*)d_in[5];
    const float* W_i   = (const float*)d_in[6];
    const float* W_f   = (const float*)d_in[7];
    const float* W_g   = (const float*)d_in[8];
    const float* W_o   = (const float*)d_in[9];
    const float* b_i   = (const float*)d_in[10];
    const float* b_f   = (const float*)d_in[11];
    const float* b_g   = (const float*)d_in[12];
    const float* b_o   = (const float*)d_in[13];
    const float* W_hy  = (const float*)d_in[14];
    const float* b_y   = (const float*)d_in[15];
    float* out = (float*)d_out;

    cudaFuncSetAttribute(hgemm_kernel<0>,
                         cudaFuncAttributeMaxDynamicSharedMemorySize, GEMM_SMEM);
    cudaFuncSetAttribute(hgemm_kernel<1>,
                         cudaFuncAttributeMaxDynamicSharedMemorySize, GEMM_SMEM);

    // 1. pack Whcat + bias
    {
        int total = H_ * G_;
        pack_kernel<<<(total + 255) / 256, 256>>>(W_i, W_f, W_g, W_o,
                                                  b_i, b_f, b_g, b_o);
    }

    // 2. weight conversions for tensor-core GEMMs
    {
        dim3 grid(V_ / 32, H_ / 32);
        dim3 blk(32, 8);
        convW_kernel<<<grid, blk>>>(W_hy);
    }
    {
        dim3 grid(H_ / 32, E_ / 32, 4);
        dim3 blk(32, 8);
        convU_kernel<<<grid, blk>>>(U_i, U_f, U_g, U_o);
    }

    // 3. gather + split embedded inputs
    gatherX_kernel<<<T_ * B_, 128>>>(embed, x_ind);

    // 4. xproj[T*B][G] = X @ U^T + bcat  (tensor cores)
    {
        dim3 grid(G_ / 128, (T_ * B_) / 128);  // (8, 32)
        hgemm_kernel<0><<<grid, 256, GEMM_SMEM>>>(nullptr, nullptr);
    }

    // 5. LSTM recurrence
    lstm_scan_v3<<<(B_ / NB) * CL_C, 256>>>();

    // 6. logits[B][T][V] = hs @ W_hy + b_y  (tensor cores)
    {
        dim3 grid(V_ / 128, (B_ * T_) / 128);  // (250, 32)
        hgemm_kernel<1><<<grid, 256, GEMM_SMEM>>>(b_y, out);
    }
}

// round 10
// speedup vs baseline: 1.2721x; 1.0668x over previous
#include <cuda_runtime.h>
#include <cuda_bf16.h>
#include <math.h>
#include <stdint.h>

#define B_ 32
#define T_ 128
#define E_ 512
#define H_ 256
#define V_ 32000
#define G_ 1024  // 4*H

// ---------------- scratch (device globals; no allocations) ----------------
__device__ float g_Whcat[H_ * G_];       // [H][4H]   1 MB
__device__ float g_bcat[G_];             // [4H]
__device__ float g_xproj[T_ * B_ * G_];  // [T][B][4H] 16 MB
__device__ __nv_bfloat16 g_Xhi[T_ * B_ * E_];   // gathered embed split, 4 MB
__device__ __nv_bfloat16 g_Xlo[T_ * B_ * E_];
__device__ __nv_bfloat16 g_Uthi[G_ * E_];       // U^T split, [G][E] 1 MB
__device__ __nv_bfloat16 g_Utlo[G_ * E_];
__device__ __nv_bfloat16 g_Ahi[B_ * T_ * H_];   // hs split, [B*T][H] 2 MB
__device__ __nv_bfloat16 g_Alo[B_ * T_ * H_];
__device__ __nv_bfloat16 g_Bthi[V_ * H_];       // W_hy^T split, [V][H] 16 MB
__device__ __nv_bfloat16 g_Btlo[V_ * H_];

// ======================= PTX helpers (sm_90-base only) =====================
__device__ __forceinline__ uint32_t smem_u32(const void* p) {
    uint32_t a;
    asm("{ .reg .u64 t; cvta.to.shared.u64 t, %1; cvt.u32.u64 %0, t; }"
        : "=r"(a) : "l"(p));
    return a;
}

__device__ __forceinline__ void cp_async16(uint32_t saddr, const void* gaddr) {
    asm volatile("cp.async.cg.shared.global [%0], [%1], 16;"
                 :: "r"(saddr), "l"(gaddr) : "memory");
}
__device__ __forceinline__ void cp_commit() {
    asm volatile("cp.async.commit_group;" ::: "memory");
}
template <int N>
__device__ __forceinline__ void cp_wait() {
    asm volatile("cp.async.wait_group %0;" :: "n"(N) : "memory");
}

__device__ __forceinline__ void ldsm_x4(uint32_t& r0, uint32_t& r1,
                                        uint32_t& r2, uint32_t& r3, uint32_t a) {
    asm volatile("ldmatrix.sync.aligned.m8n8.x4.shared.b16 {%0,%1,%2,%3}, [%4];"
                 : "=r"(r0), "=r"(r1), "=r"(r2), "=r"(r3) : "r"(a));
}
__device__ __forceinline__ void ldsm_x2(uint32_t& r0, uint32_t& r1, uint32_t a) {
    asm volatile("ldmatrix.sync.aligned.m8n8.x2.shared.b16 {%0,%1}, [%2];"
                 : "=r"(r0), "=r"(r1) : "r"(a));
}

__device__ __forceinline__ void mma_bf16(float* d, const uint32_t* a,
                                         const uint32_t* b) {
    asm volatile(
        "mma.sync.aligned.m16n8k16.row.col.f32.bf16.bf16.f32 "
        "{%0,%1,%2,%3}, {%4,%5,%6,%7}, {%8,%9}, {%0,%1,%2,%3};"
        : "+f"(d[0]), "+f"(d[1]), "+f"(d[2]), "+f"(d[3])
        : "r"(a[0]), "r"(a[1]), "r"(a[2]), "r"(a[3]), "r"(b[0]), "r"(b[1]));
}

#define CLUSTER_SYNC() do { \
    asm volatile("barrier.cluster.arrive.aligned;" ::: "memory"); \
    asm volatile("barrier.cluster.wait.aligned;" ::: "memory"); \
} while (0)

__device__ __forceinline__ uint32_t mapa_cluster(uint32_t local, uint32_t rank) {
    uint32_t r;
    asm volatile("mapa.shared::cluster.u32 %0, %1, %2;" : "=r"(r) : "r"(local), "r"(rank));
    return r;
}
__device__ __forceinline__ void st_cluster_f32(uint32_t addr, float v) {
    asm volatile("st.shared::cluster.f32 [%0], %1;" :: "r"(addr), "f"(v) : "memory");
}

// ---------------- pack Whcat + bias (scan uses fp32 weights) ---------------
__global__ void pack_kernel(const float* __restrict__ Wi, const float* __restrict__ Wf,
                            const float* __restrict__ Wg, const float* __restrict__ Wo,
                            const float* __restrict__ bi, const float* __restrict__ bf,
                            const float* __restrict__ bg, const float* __restrict__ bo)
{
    int i = blockIdx.x * blockDim.x + threadIdx.x;
    if (i < H_ * G_) {
        int k = i / G_, j = i % G_;
        int g = j / H_, jj = j % H_;
        const float* W = (g == 0) ? Wi : (g == 1) ? Wf : (g == 2) ? Wg : Wo;
        g_Whcat[i] = W[k * H_ + jj];
    }
    if (i < G_) {
        int g = i / H_, jj = i % H_;
        const float* bb = (g == 0) ? bi : (g == 1) ? bf : (g == 2) ? bg : bo;
        g_bcat[i] = bb[jj];
    }
}

// --------- transpose + bf16-split W_hy [H][V] -> Bt_hi/Bt_lo [V][H] ---------
__global__ void convW_kernel(const float* __restrict__ W_hy)
{
    __shared__ float tl[32][33];
    int v0 = blockIdx.x * 32, k0 = blockIdx.y * 32;
    int tx = threadIdx.x, ty = threadIdx.y;
#pragma unroll
    for (int i = 0; i < 4; i++) {
        int k = ty + i * 8;
        tl[k][tx] = W_hy[(size_t)(k0 + k) * V_ + v0 + tx];
    }
    __syncthreads();
#pragma unroll
    for (int i = 0; i < 4; i++) {
        int vr = ty + i * 8;
        float x = tl[tx][vr];
        __nv_bfloat16 hi = __float2bfloat16(x);
        __nv_bfloat16 lo = __float2bfloat16(x - __bfloat162float(hi));
        size_t o = (size_t)(v0 + vr) * H_ + k0 + tx;
        g_Bthi[o] = hi;
        g_Btlo[o] = lo;
    }
}

// --------- transpose + bf16-split gate U [E][H] -> Ut_hi/lo [G][E] ----------
__global__ void convU_kernel(const float* __restrict__ Ui, const float* __restrict__ Uf,
                             const float* __restrict__ Ug, const float* __restrict__ Uo)
{
    __shared__ float tl[32][33];
    const int gate = blockIdx.z;
    const float* U = (gate == 0) ? Ui : (gate == 1) ? Uf : (gate == 2) ? Ug : Uo;
    int h0 = blockIdx.x * 32, e0 = blockIdx.y * 32;
    int tx = threadIdx.x, ty = threadIdx.y;
#pragma unroll
    for (int i = 0; i < 4; i++) {
        int e = ty + i * 8;
        tl[e][tx] = U[(size_t)(e0 + e) * H_ + h0 + tx];
    }
    __syncthreads();
#pragma unroll
    for (int i = 0; i < 4; i++) {
        int hr = ty + i * 8;
        float x = tl[tx][hr];
        __nv_bfloat16 hi = __float2bfloat16(x);
        __nv_bfloat16 lo = __float2bfloat16(x - __bfloat162float(hi));
        size_t o = (size_t)(gate * H_ + h0 + hr) * E_ + e0 + tx;
        g_Uthi[o] = hi;
        g_Utlo[o] = lo;
    }
}

// --------- gather embed rows + bf16-split: X[r=t*B+b][E] ----------
__global__ void gatherX_kernel(const float* __restrict__ embed,
                               const int* __restrict__ xind)
{
    const int r = blockIdx.x;          // 0..T*B-1, r = t*B + b
    const int t = r / B_, b = r % B_;
    const float* src = embed + (size_t)xind[b * T_ + t] * E_;
    for (int i = threadIdx.x * 4; i < E_; i += blockDim.x * 4) {
        float4 v = *reinterpret_cast<const float4*>(src + i);
        __nv_bfloat16 h0 = __float2bfloat16(v.x);
        __nv_bfloat16 h1 = __float2bfloat16(v.y);
        __nv_bfloat16 h2 = __float2bfloat16(v.z);
        __nv_bfloat16 h3 = __float2bfloat16(v.w);
        __nv_bfloat162 hi01 = {h0, h1}, hi23 = {h2, h3};
        __nv_bfloat162 lo01 = {__float2bfloat16(v.x - __bfloat162float(h0)),
                               __float2bfloat16(v.y - __bfloat162float(h1))};
        __nv_bfloat162 lo23 = {__float2bfloat16(v.z - __bfloat162float(h2)),
                               __float2bfloat16(v.w - __bfloat162float(h3))};
        *reinterpret_cast<__nv_bfloat162*>(g_Xhi + (size_t)r * E_ + i)     = hi01;
        *reinterpret_cast<__nv_bfloat162*>(g_Xhi + (size_t)r * E_ + i + 2) = hi23;
        *reinterpret_cast<__nv_bfloat162*>(g_Xlo + (size_t)r * E_ + i)     = lo01;
        *reinterpret_cast<__nv_bfloat162*>(g_Xlo + (size_t)r * E_ + i + 2) = lo23;
    }
}

// ===== LSTM recurrence v4: 4 cols x 32 k per thread (LDS-traffic / 4) ======
// Cluster of 8 CTAs, 2 batches. CTA rank owns h-slice [rank*32, rank*32+32)
// -> 128 z-cols. 256 threads: kg = tid>>5 (32-k block), cg = tid&31
// (4 consecutive cols). wreg[32] float4, coalesced.
// Per step: dot (8 indep 32-deep chains, 16 LDS.128/thread) -> 1 sync ->
// reduce+gates on 64 threads -> DSMEM broadcast -> 1 cluster sync.
#define CL_C 8
#define NB 2

__global__ void __cluster_dims__(CL_C, 1, 1) __launch_bounds__(256, 1)
lstm_scan_v4()
{
    __shared__ float h_s[2 * NB * 256];     // [buf][batch][256]
    __shared__ float zp_s[8 * NB * 128];    // [kg][batch][col]

    const int tid = threadIdx.x;
    uint32_t rank;
    asm("mov.u32 %0, %%cluster_ctarank;" : "=r"(rank));
    const int cid = blockIdx.x / CL_C;

    const int kg = tid >> 5;          // 32-k block 0..7
    const int cg = tid & 31;          // 4-col group 0..31
    const int gate0 = cg >> 3;        // gate of these 4 cols
    const int s0    = (cg & 7) * 4;   // slice col base
    const int gcol0 = gate0 * H_ + (int)rank * 32 + s0;

    // register-resident weights: wreg[k] = Whcat[kg*32+k][gcol0..gcol0+3]
    float4 wreg[32];
    {
        const float* wp = g_Whcat + (size_t)(kg * 32) * G_ + gcol0;
#pragma unroll
        for (int k = 0; k < 32; k++)
            wreg[k] = *reinterpret_cast<const float4*>(wp + (size_t)k * G_);
    }

    for (int i = tid; i < 2 * NB * 256; i += 256) h_s[i] = 0.f;
    CLUSTER_SYNC();

    const int bgl0 = cid * NB;

    // gate-phase identity (threads 0..63)
    const int gb = tid >> 5;   // batch (valid when tid<64)
    const int gs = tid & 31;   // slice col
    float c_reg = 0.f;

    for (int t = 0; t < T_; t++) {
        const int p = t & 1;

        // xproj prefetch for gate threads (consumed after the dot)
        float xpi = 0.f, xpf = 0.f, xpg = 0.f, xpo = 0.f;
        if (tid < 64) {
            const float* xb = g_xproj + (size_t)(t * B_ + bgl0 + gb) * G_ +
                              (int)rank * 32 + gs;
            xpi = xb[0];
            xpf = xb[H_];
            xpg = xb[2 * H_];
            xpo = xb[3 * H_];
        }

        // ---- dot: 4 cols x 2 batches over this thread's 32-k block ----
        const float* h0p = h_s + p * (NB * 256) + kg * 32;
        const float* h1p = h0p + 256;
        float4 a0 = make_float4(0.f, 0.f, 0.f, 0.f);
        float4 a1 = make_float4(0.f, 0.f, 0.f, 0.f);
#pragma unroll
        for (int i = 0; i < 8; i++) {
            float4 v0 = *reinterpret_cast<const float4*>(h0p + i * 4);
            float4 v1 = *reinterpret_cast<const float4*>(h1p + i * 4);
#pragma unroll
            for (int kk = 0; kk < 4; kk++) {
                float4 w = wreg[i * 4 + kk];
                float e0 = (kk == 0) ? v0.x : (kk == 1) ? v0.y : (kk == 2) ? v0.z : v0.w;
                float e1 = (kk == 0) ? v1.x : (kk == 1) ? v1.y : (kk == 2) ? v1.z : v1.w;
                a0.x += e0 * w.x; a0.y += e0 * w.y; a0.z += e0 * w.z; a0.w += e0 * w.w;
                a1.x += e1 * w.x; a1.y += e1 * w.y; a1.z += e1 * w.z; a1.w += e1 * w.w;
            }
        }
        *reinterpret_cast<float4*>(zp_s + (kg * NB + 0) * 128 + cg * 4) = a0;
        *reinterpret_cast<float4*>(zp_s + (kg * NB + 1) * 128 + cg * 4) = a1;
        __syncthreads();

        // ---- reduce 8 k-blocks + gates (threads 0..63: (gb, gs)) ----
        if (tid < 64) {
            float zi = xpi, zf = xpf, zg = xpg, zo = xpo;
#pragma unroll
            for (int q = 0; q < 8; q++) {
                const float* base = zp_s + (q * NB + gb) * 128;
                zi += base[gs];
                zf += base[32 + gs];
                zg += base[64 + gs];
                zo += base[96 + gs];
            }
            float ig = 1.f / (1.f + expf(-zi));
            float fg = 1.f / (1.f + expf(-zf));
            float gv = tanhf(zg);
            float og = 1.f / (1.f + expf(-zo));
            c_reg = fg * c_reg + ig * gv;
            float h = og * tanhf(c_reg);

            // bf16 hi/lo output for logits GEMM
            int bg = bgl0 + gb;
            __nv_bfloat16 hi = __float2bfloat16(h);
            __nv_bfloat16 lo = __float2bfloat16(h - __bfloat162float(hi));
            size_t o = ((size_t)bg * T_ + t) * H_ + rank * 32 + gs;
            g_Ahi[o] = hi;
            g_Alo[o] = lo;

            // broadcast to all 8 CTAs' next h buffer
            const int q2 = p ^ 1;
            uint32_t la = smem_u32(h_s + q2 * (NB * 256) + gb * 256 +
                                   (int)rank * 32 + gs);
#pragma unroll
            for (int rk = 0; rk < CL_C; rk++)
                st_cluster_f32(mapa_cluster(la, (uint32_t)rk), h);
        }
        CLUSTER_SYNC();
    }
}

// ======== HGEMM template: binds device globals INSIDE device code ==========
// MODE 0: g_xproj[T*B][G]  = (Xhi+Xlo) @ (Uthi+Utlo)^T + g_bcat   (K=512)
// MODE 1: out[B*T][V]      = (Ahi+Alo) @ (Bthi+Btlo)^T + b_y      (K=256)
#define BK 32
#define SROW 40                       // padded row stride (bf16 elems) = 80B
#define TILE_SB (128 * SROW * 2)      // 10240 B per matrix per stage
#define STAGE_SB (4 * TILE_SB)        // Ahi,Alo,Bhi,Blo
#define GEMM_SMEM (2 * STAGE_SB)      // 81920 B

template <int MODE>
__global__ __launch_bounds__(256, 2) void hgemm_kernel(
    const float* __restrict__ bias_ext, float* __restrict__ out_ext)
{
    constexpr int NDIM = (MODE == 0) ? G_ : V_;
    constexpr int KDIM = (MODE == 0) ? E_ : H_;
    constexpr int NSTG = KDIM / BK;

    extern __shared__ char smem[];
    const uint32_t sb = smem_u32(smem);
    const int tid  = threadIdx.x;
    const int lane = tid & 31;
    const int wid  = tid >> 5;
    const int wm   = wid >> 2;
    const int wn   = wid & 3;

    const int row0 = blockIdx.y * 128;
    const int col0 = blockIdx.x * 128;

    const __nv_bfloat16* Ahi = (MODE == 0) ? g_Xhi  : g_Ahi;
    const __nv_bfloat16* Alo = (MODE == 0) ? g_Xlo  : g_Alo;
    const __nv_bfloat16* Bhi = (MODE == 0) ? g_Uthi : g_Bthi;
    const __nv_bfloat16* Blo = (MODE == 0) ? g_Utlo : g_Btlo;
    const float* bias = (MODE == 0) ? g_bcat  : bias_ext;
    float*       out  = (MODE == 0) ? g_xproj : out_ext;

    const int ld_r   = tid >> 2;
    const int ld_seg = tid & 3;
    const __nv_bfloat16* gsrc[4];
    gsrc[0] = Ahi + (size_t)(row0)*KDIM;
    gsrc[1] = Alo + (size_t)(row0)*KDIM;
    gsrc[2] = Bhi + (size_t)(col0)*KDIM;
    gsrc[3] = Blo + (size_t)(col0)*KDIM;

    float acc[4][4][4];
#pragma unroll
    for (int i = 0; i < 4; i++)
#pragma unroll
        for (int j = 0; j < 4; j++)
#pragma unroll
            for (int r = 0; r < 4; r++) acc[i][j][r] = 0.f;

#pragma unroll
    for (int m = 0; m < 4; m++)
#pragma unroll
        for (int h = 0; h < 2; h++) {
            int r = ld_r + h * 64;
            uint32_t sa = sb + 0 * STAGE_SB + m * TILE_SB + r * (SROW * 2) + ld_seg * 16;
            cp_async16(sa, gsrc[m] + (size_t)r * KDIM + 0 * BK + ld_seg * 8);
        }
    cp_commit();

    for (int s = 0; s < NSTG; s++) {
        if (s + 1 < NSTG) {
            int buf = (s + 1) & 1;
#pragma unroll
            for (int m = 0; m < 4; m++)
#pragma unroll
                for (int h = 0; h < 2; h++) {
                    int r = ld_r + h * 64;
                    uint32_t sa = sb + buf * STAGE_SB + m * TILE_SB +
                                  r * (SROW * 2) + ld_seg * 16;
                    cp_async16(sa, gsrc[m] + (size_t)r * KDIM + (s + 1) * BK + ld_seg * 8);
                }
            cp_commit();
            cp_wait<1>();
        } else {
            cp_wait<0>();
        }
        __syncthreads();

        const uint32_t base = sb + (s & 1) * STAGE_SB;
        const uint32_t sAhi = base;
        const uint32_t sAlo = base + TILE_SB;
        const uint32_t sBhi = base + 2 * TILE_SB;
        const uint32_t sBlo = base + 3 * TILE_SB;

#pragma unroll
        for (int kk = 0; kk < 2; kk++) {
            uint32_t bhi[4][2], blo[4][2];
            const int b_row_l = (lane & 7);
            const int b_col   = kk * 16 + ((lane >> 3) & 1) * 8;
#pragma unroll
            for (int nt = 0; nt < 4; nt++) {
                int r = wn * 32 + nt * 8 + b_row_l;
                uint32_t off = (uint32_t)(r * (SROW * 2) + b_col * 2);
                ldsm_x2(bhi[nt][0], bhi[nt][1], sBhi + off);
                ldsm_x2(blo[nt][0], blo[nt][1], sBlo + off);
            }
            const int a_row_l = (lane & 15);
            const int a_col   = kk * 16 + (lane >> 4) * 8;
#pragma unroll
            for (int mt = 0; mt < 4; mt++) {
                uint32_t ahi[4], alo[4];
                int r = wm * 64 + mt * 16 + a_row_l;
                uint32_t off = (uint32_t)(r * (SROW * 2) + a_col * 2);
                ldsm_x4(ahi[0], ahi[1], ahi[2], ahi[3], sAhi + off);
                ldsm_x4(alo[0], alo[1], alo[2], alo[3], sAlo + off);
#pragma unroll
                for (int nt = 0; nt < 4; nt++) {
                    mma_bf16(acc[mt][nt], ahi, bhi[nt]);
                    mma_bf16(acc[mt][nt], ahi, blo[nt]);
                    mma_bf16(acc[mt][nt], alo, bhi[nt]);
                }
            }
        }
        __syncthreads();
    }

    const int er = lane >> 2;
    const int ec = (lane & 3) * 2;
#pragma unroll
    for (int mt = 0; mt < 4; mt++) {
#pragma unroll
        for (int nt = 0; nt < 4; nt++) {
            int col = col0 + wn * 32 + nt * 8 + ec;
            float bx = bias[col], by = bias[col + 1];
            int r0 = row0 + wm * 64 + mt * 16 + er;
            float2 v0 = make_float2(acc[mt][nt][0] + bx, acc[mt][nt][1] + by);
            float2 v1 = make_float2(acc[mt][nt][2] + bx, acc[mt][nt][3] + by);
            *reinterpret_cast<float2*>(out + (size_t)r0 * NDIM + col) = v0;
            *reinterpret_cast<float2*>(out + (size_t)(r0 + 8) * NDIM + col) = v1;
        }
    }
}

// ---------------- launch ----------------
extern "C" void kernel_launch(void* const* d_in, const int* in_sizes, int n_in,
                              void* d_out, int out_size)
{
    const int*   x_ind = (const int*)  d_in[0];
    const float* embed = (const float*)d_in[1];
    const float* U_i   = (const float*)d_in[2];
    const float* U_f   = (const float*)d_in[3];
    const float* U_g   = (const float*)d_in[4];
    const float* U_o   = (const float*)d_in[5];
    const float* W_i   = (const float*)d_in[6];
    const float* W_f   = (const float*)d_in[7];
    const float* W_g   = (const float*)d_in[8];
    const float* W_o   = (const float*)d_in[9];
    const float* b_i   = (const float*)d_in[10];
    const float* b_f   = (const float*)d_in[11];
    const float* b_g   = (const float*)d_in[12];
    const float* b_o   = (const float*)d_in[13];
    const float* W_hy  = (const float*)d_in[14];
    const float* b_y   = (const float*)d_in[15];
    float* out = (float*)d_out;

    cudaFuncSetAttribute(hgemm_kernel<0>,
                         cudaFuncAttributeMaxDynamicSharedMemorySize, GEMM_SMEM);
    cudaFuncSetAttribute(hgemm_kernel<1>,
                         cudaFuncAttributeMaxDynamicSharedMemorySize, GEMM_SMEM);

    // 1. pack Whcat + bias
    {
        int total = H_ * G_;
        pack_kernel<<<(total + 255) / 256, 256>>>(W_i, W_f, W_g, W_o,
                                                  b_i, b_f, b_g, b_o);
    }

    // 2. weight conversions for tensor-core GEMMs
    {
        dim3 grid(V_ / 32, H_ / 32);
        dim3 blk(32, 8);
        convW_kernel<<<grid, blk>>>(W_hy);
    }
    {
        dim3 grid(H_ / 32, E_ / 32, 4);
        dim3 blk(32, 8);
        convU_kernel<<<grid, blk>>>(U_i, U_f, U_g, U_o);
    }

    // 3. gather + split embedded inputs
    gatherX_kernel<<<T_ * B_, 128>>>(embed, x_ind);

    // 4. xproj[T*B][G] = X @ U^T + bcat  (tensor cores)
    {
        dim3 grid(G_ / 128, (T_ * B_) / 128);  // (8, 32)
        hgemm_kernel<0><<<grid, 256, GEMM_SMEM>>>(nullptr, nullptr);
    }

    // 5. LSTM recurrence v4
    lstm_scan_v4<<<(B_ / NB) * CL_C, 256>>>();

    // 6. logits[B][T][V] = hs @ W_hy + b_y  (tensor cores)
    {
        dim3 grid(V_ / 128, (B_ * T_) / 128);  // (250, 32)
        hgemm_kernel<1><<<grid, 256, GEMM_SMEM>>>(b_y, out);
    }
}